// round 9
// baseline (speedup 1.0000x reference)
#include <cuda_runtime.h>
#include <float.h>

// WOS: weighted order statistic, O(D^2/2) symmetric rank-by-counting.
// R6 algorithm (best: 107.3us) with occupancy forced to 4 blocks/SM:
// __launch_bounds__(128, 4) caps regs at 128 (was 168 -> 12 warps/SM).
// Issue efficiency was pinned at ~64% with 3 warps/SMSP; 16 warps should
// lift it to ~75-80% at the cost of ~30-40 cold spills.

#define NCH   16
#define DTOT  54
#define DHALF 27
#define TOL   1e-6f
#define JT    18          // j-tile size (3 tiles)
#define PX    8           // pixels per block

// i < j by iteration order: ties (>=) put i before j (stable argsort).
// Winner's weight charged to the loser's accumulator.
__device__ __forceinline__ void pair_update(float& accj, float& acci,
                                            float mi, float mj,
                                            float wi, float wj) {
    asm volatile("{\n\t"
        ".reg .pred p;\n\t"
        "setp.ge.f32 p, %2, %3;\n\t"
        "@p  add.f32 %0, %0, %4;\n\t"
        "@!p add.f32 %1, %1, %5;\n\t"
        "}" : "+f"(accj), "+f"(acci)
            : "f"(mi), "f"(mj), "f"(wi), "f"(wj));
}

__global__ __launch_bounds__(128, 4)
void wos_kernel(const float* __restrict__ x,
                const float* __restrict__ mask,
                const float* __restrict__ weight,
                const float* __restrict__ bias,
                float* __restrict__ out)
{
    __shared__ float msk[NCH * DTOT];       // mask per nc
    __shared__ float wgs[NCH * DTOT];       // gated weights: w>tol ? w : 0
    __shared__ float ptile[3][3][PX + 2];   // [c][kh][col] halo for PX pixels

    const int tid = threadIdx.x + threadIdx.y * 16;   // x = nc(16), y = pixel(PX)

    for (int e = tid; e < NCH * DTOT; e += 128) {
        msk[e] = mask[e];
        float w = weight[e];
        wgs[e] = (w > TOL) ? w : 0.0f;
    }

    const int n0  = blockIdx.x * PX;        // PX consecutive pixels, same (b,h)
    const int b   = n0 >> 12;
    const int rem = n0 & 4095;
    const int h   = rem >> 6;
    const int w0  = rem & 63;

    for (int e = tid; e < 3 * 3 * (PX + 2); e += 128) {
        int c   = e / (3 * (PX + 2));
        int r   = (e / (PX + 2)) % 3;
        int col = e % (PX + 2);
        int gr  = h - 1 + r;
        int gc  = w0 - 1 + col;
        float v = 0.0f;
        if ((unsigned)gr < 64u && (unsigned)gc < 64u)
            v = x[((b * 3 + c) * 64 + gr) * 64 + gc];
        ptile[c][r][col] = v;
    }
    __syncthreads();

    const int nc = threadIdx.x;
    const int py = threadIdx.y;
    const int n  = n0 + py;
    const int mb = nc * DTOT;

    // ---- mx[54] = [p, -p] + mask[nc] ----
    float mx[DTOT];
    #pragma unroll
    for (int c = 0; c < 3; c++)
        #pragma unroll
        for (int r = 0; r < 3; r++)
            #pragma unroll
            for (int kw = 0; kw < 3; kw++) {
                int d = c * 9 + r * 3 + kw;
                float p = ptile[c][r][py + kw];
                mx[d]         = p + msk[mb + d];
                mx[d + DHALF] = msk[mb + d + DHALF] - p;
            }

    // ---- inclusive accumulators start at own gated weight ----
    float acc[DTOT];
    #pragma unroll
    for (int d = 0; d < DTOT; d++)
        acc[d] = wgs[mb + d];

    // ---- symmetric pair loop, j tiled by JT ----
    #pragma unroll
    for (int t = 0; t < DTOT / JT; t++) {
        const int J0 = t * JT;
        float wj[JT];
        #pragma unroll
        for (int jj = 0; jj < JT; jj++)
            wj[jj] = wgs[mb + J0 + jj];

        #pragma unroll
        for (int i = 0; i < J0 + JT; i++) {
            float mi = mx[i];
            float wi = (i >= J0) ? wj[i - J0] : wgs[mb + i];  // compile-time pick
            #pragma unroll
            for (int jj = 0; jj < JT; jj++) {
                int j = J0 + jj;
                if (j > i)
                    pair_update(acc[j], acc[i], mi, mx[j], wi, wj[jj]);
            }
        }
    }

    // ---- selection epilogue ----
    const float biasv = bias[nc];
    float selMin = FLT_MAX;
    float fbMax  = -FLT_MAX;
    int found = 0, anynz = 0;

    #pragma unroll
    for (int j = 0; j < DTOT; j++) {
        float wjv = wgs[mb + j];
        if (wjv > 0.0f) {
            anynz = 1;
            float vj = mx[j];
            fbMax = fmaxf(fbMax, vj);
            if (acc[j] <= biasv) {
                found = 1;
                selMin = fminf(selMin, vj);
            }
        }
    }

    float res = found ? selMin : (anynz ? fbMax : 0.0f);
    out[n * NCH + nc] = res;    // flat layout: coalesced per warp
}

extern "C" void kernel_launch(void* const* d_in, const int* in_sizes, int n_in,
                              void* d_out, int out_size) {
    const float* x      = (const float*)d_in[0];
    const float* mask   = (const float*)d_in[1];
    const float* weight = (const float*)d_in[2];
    const float* bias   = (const float*)d_in[3];
    float* out = (float*)d_out;

    // 32768 pixels / 8 per block = 4096 blocks; block = 16 nc x 8 pixels
    wos_kernel<<<4096, dim3(16, PX)>>>(x, mask, weight, bias, out);
}

// round 10
// speedup vs baseline: 1.3380x; 1.3380x over previous
#include <cuda_runtime.h>
#include <float.h>

// WOS: O(D^2/2) symmetric rank-by-counting, two-phase tiling.
// D=54 split into two 27-halves so at most one half's (mx, acc, w) is
// register-resident at a time (~100 regs vs 168 monolithic). Tile0 state is
// parked in per-thread smem between phases. 16 warps/SM without spills.

#define NCH   16
#define DTOT  54
#define DHALF 27
#define TOL   1e-6f
#define PX    8           // pixels per block

// i < j by construction: ties (>=) put i before j (stable argsort).
// Winner's weight charged to the loser's accumulator (s aliases acc_i).
__device__ __forceinline__ void pair_update(float& accj, float& acci,
                                            float mi, float mj,
                                            float wi, float wj) {
    asm volatile("{\n\t"
        ".reg .pred p;\n\t"
        "setp.ge.f32 p, %2, %3;\n\t"
        "@p  add.f32 %0, %0, %4;\n\t"
        "@!p add.f32 %1, %1, %5;\n\t"
        "}" : "+f"(accj), "+f"(acci)
            : "f"(mi), "f"(mj), "f"(wi), "f"(wj));
}

__global__ __launch_bounds__(128, 4)
void wos_kernel(const float* __restrict__ x,
                const float* __restrict__ mask,
                const float* __restrict__ weight,
                const float* __restrict__ bias,
                float* __restrict__ out)
{
    __shared__ float msk[NCH * DTOT];        // mask per nc
    __shared__ float wgs[NCH * DTOT];        // gated weights: w>tol ? w : 0
    __shared__ float ptile[3][3][PX + 2];    // halo tile for PX pixels
    __shared__ float mxs[128 * DHALF];       // per-thread tile0 mx (stride 27: conflict-free)
    __shared__ float accs[128 * DHALF];      // per-thread tile0 acc

    const int tid = threadIdx.x + threadIdx.y * 16;   // x = nc(16), y = pixel(PX)

    for (int e = tid; e < NCH * DTOT; e += 128) {
        msk[e] = mask[e];
        float w = weight[e];
        wgs[e] = (w > TOL) ? w : 0.0f;
    }

    const int n0  = blockIdx.x * PX;         // PX consecutive pixels, same (b,h)
    const int b   = n0 >> 12;
    const int rem = n0 & 4095;
    const int h   = rem >> 6;
    const int w0  = rem & 63;

    for (int e = tid; e < 3 * 3 * (PX + 2); e += 128) {
        int c   = e / (3 * (PX + 2));
        int r   = (e / (PX + 2)) % 3;
        int col = e % (PX + 2);
        int gr  = h - 1 + r;
        int gc  = w0 - 1 + col;
        float v = 0.0f;
        if ((unsigned)gr < 64u && (unsigned)gc < 64u)
            v = x[((b * 3 + c) * 64 + gr) * 64 + gc];
        ptile[c][r][col] = v;
    }
    __syncthreads();

    const int nc = threadIdx.x;
    const int py = threadIdx.y;
    const int n  = n0 + py;
    const int mb = nc * DTOT;
    const int sb = tid * DHALF;              // this thread's smem slice

    float mxt[DHALF], acct[DHALF], wt[DHALF];

    // ================= Phase A: tile0 (d = 0..26, mx = p + mask) =================
    #pragma unroll
    for (int c = 0; c < 3; c++)
        #pragma unroll
        for (int r = 0; r < 3; r++)
            #pragma unroll
            for (int kw = 0; kw < 3; kw++) {
                int d = c * 9 + r * 3 + kw;
                mxt[d]  = ptile[c][r][py + kw] + msk[mb + d];
                wt[d]   = wgs[mb + d];
                acct[d] = wt[d];             // inclusive: starts at own weight
            }

    #pragma unroll
    for (int i = 0; i < DHALF - 1; i++)
        #pragma unroll
        for (int j = i + 1; j < DHALF; j++)
            pair_update(acct[j], acct[i], mxt[i], mxt[j], wt[i], wt[j]);

    #pragma unroll
    for (int d = 0; d < DHALF; d++) {        // park tile0 in smem
        mxs[sb + d]  = mxt[d];
        accs[sb + d] = acct[d];
    }

    // ================= Phase B: tile1 (d = 27..53, mx = mask - p) ================
    #pragma unroll
    for (int c = 0; c < 3; c++)
        #pragma unroll
        for (int r = 0; r < 3; r++)
            #pragma unroll
            for (int kw = 0; kw < 3; kw++) {
                int d = c * 9 + r * 3 + kw;
                mxt[d]  = msk[mb + DHALF + d] - ptile[c][r][py + kw];
                wt[d]   = wgs[mb + DHALF + d];
                acct[d] = wt[d];
            }

    #pragma unroll
    for (int i = 0; i < DHALF - 1; i++)
        #pragma unroll
        for (int j = i + 1; j < DHALF; j++)
            pair_update(acct[j], acct[i], mxt[i], mxt[j], wt[i], wt[j]);

    // cross pairs: global i in tile0 (< 27) vs j in tile1 (>= 27): always i < j
    #pragma unroll
    for (int i = 0; i < DHALF; i++) {
        float mi = mxs[sb + i];
        float wi = wgs[mb + i];
        float s  = 0.0f;                     // loser-side partial for acc0[i]
        #pragma unroll
        for (int jj = 0; jj < DHALF; jj++)
            pair_update(acct[jj], s, mi, mxt[jj], wi, wt[jj]);
        accs[sb + i] += s;                   // one RMW per i
    }

    // ================= selection epilogue =================
    const float biasv = bias[nc];
    float selMin = FLT_MAX;
    float fbMax  = -FLT_MAX;
    int found = 0, anynz = 0;

    #pragma unroll
    for (int j = 0; j < DHALF; j++) {        // tile0 from smem
        float wjv = wgs[mb + j];
        if (wjv > 0.0f) {
            anynz = 1;
            float vj = mxs[sb + j];
            fbMax = fmaxf(fbMax, vj);
            if (accs[sb + j] <= biasv) { found = 1; selMin = fminf(selMin, vj); }
        }
    }
    #pragma unroll
    for (int j = 0; j < DHALF; j++) {        // tile1 from regs
        if (wt[j] > 0.0f) {
            anynz = 1;
            float vj = mxt[j];
            fbMax = fmaxf(fbMax, vj);
            if (acct[j] <= biasv) { found = 1; selMin = fminf(selMin, vj); }
        }
    }

    float res = found ? selMin : (anynz ? fbMax : 0.0f);
    out[n * NCH + nc] = res;                 // flat layout: coalesced per warp
}

extern "C" void kernel_launch(void* const* d_in, const int* in_sizes, int n_in,
                              void* d_out, int out_size) {
    const float* x      = (const float*)d_in[0];
    const float* mask   = (const float*)d_in[1];
    const float* weight = (const float*)d_in[2];
    const float* bias   = (const float*)d_in[3];
    float* out = (float*)d_out;

    // 32768 pixels / 8 per block = 4096 blocks; block = 16 nc x 8 pixels
    wos_kernel<<<4096, dim3(16, PX)>>>(x, mask, weight, bias, out);
}